// round 10
// baseline (speedup 1.0000x reference)
#include <cuda_runtime.h>
#include <cstdint>

// Problem constants
constexpr int Bc = 8, Lc = 4096;
constexpr int Mrows = Bc * Lc;          // 32768
constexpr int NCHUNK = 64, CLEN = 64;   // 64 chunks of 64 steps

// Scratch (static device arrays -- no allocation allowed)
__device__ float g_f [(size_t)Mrows * 512];   // f = dt_s*Bu : [bl][2p+c] (re/im interleaved)
__device__ float g_ys[(size_t)Mrows * 512];   // ys, same interleaved layout
// Fragment-packed MMA-B operands: [k8][j(n8)][lane(32)*2]
__device__ float g_BopP[256 * 512];           // GEMM1 B: K=256(h), N=512(2p+c): 32 k8 x 64 j
__device__ float g_CopP[512 * 256];           // GEMM2 B: K=512(2p+c), N=256(h): 64 k8 x 32 j
__device__ float g_m11[256], g_m12[256], g_dts[256];
__device__ float g_cf  [Bc * 256 * NCHUNK * 4]; // [b][p][ch] float4 (x1r,x1i,x2r,x2i)
__device__ float g_init[Bc * 256 * NCHUNK * 4]; // same layout

__device__ __forceinline__ float tf32_rna(float x) {
    uint32_t u;
    asm("cvt.rna.tf32.f32 %0, %1;" : "=r"(u) : "f"(x));
    return __uint_as_float(u);
}

__device__ __forceinline__ void cp_async16(void* smem, const void* gmem) {
    uint32_t s = (uint32_t)__cvta_generic_to_shared(smem);
    asm volatile("cp.async.ca.shared.global [%0], [%1], 16;\n" :: "r"(s), "l"(gmem));
}

__device__ __forceinline__ void mma_tf32_v(float c[4], const uint32_t a[4], const uint32_t b[2]) {
    asm volatile(
        "mma.sync.aligned.m16n8k8.row.col.f32.tf32.tf32.f32 "
        "{%0,%1,%2,%3}, {%4,%5,%6,%7}, {%8,%9}, {%0,%1,%2,%3};\n"
        : "+f"(c[0]), "+f"(c[1]), "+f"(c[2]), "+f"(c[3])
        : "r"(a[0]), "r"(a[1]), "r"(a[2]), "r"(a[3]), "r"(b[0]), "r"(b[1]));
}

// ---------------------------------------------------------------------------
// Prep: per-p recurrence params + fragment-packed operand matrices (tf32 RNA)
// Fragment layout (B operand of m16n8k8, k x n): element (k, n) at
//   ((k>>3)*NJ + (n>>3))*64 + ((n&7)*4 + (k&3))*2 + ((k>>2)&1)
// ---------------------------------------------------------------------------
__global__ void prep_kernel(const float* __restrict__ Ad, const float* __restrict__ Gd,
                            const float* __restrict__ dt, const float* __restrict__ Bm,
                            const float* __restrict__ Cm) {
    int h = blockIdx.x;          // 0..255
    int n = threadIdx.x;         // 0..511
    int p = n >> 1;
    int c = n & 1;
    float dts = 1.0f / (1.0f + expf(-dt[p]));
    float G = fmaxf(Gd[p], dts * Ad[p]);
    float A = fmaxf(Ad[p], 0.25f * G * G);

    // GEMM1 B: k=h (K=256), n=2p+c (N=512), NJ=64
    g_BopP[((h >> 3) * 64 + (n >> 3)) * 64 + ((n & 7) * 4 + (h & 3)) * 2 + ((h >> 2) & 1)]
        = tf32_rna(dts * Bm[p * 512 + h * 2 + c]);
    // GEMM2 B: k=2p+c (K=512), n=h (N=256), NJ=32
    float cv = Cm[h * 512 + p * 2 + c];
    g_CopP[((n >> 3) * 32 + (h >> 3)) * 64 + ((h & 7) * 4 + (n & 3)) * 2 + ((n >> 2) & 1)]
        = tf32_rna(c ? -cv : cv);

    if (h == 0 && c == 0) {
        g_m11[p] = 1.0f - dts * G;
        g_m12[p] = -dts * A;
        g_dts[p] = dts;          // m21; m22 == 1
    }
}

// ---------------------------------------------------------------------------
// Big-tile tf32 GEMM: C[M x N] = A[M x K] @ B + (D*u epilogue | fused local scan)
// Block tile 128x256x32, 8 warps (2m x 4n), warp tile 64x64 (mt=4, nt=8).
// A: round-2 path (ldg -> tf32-round -> smem stride-36, scalar frag loads).
// B: fragment-packed gmem -> cp.async -> LDS.64 frag loads.
// smem: As 2*4608 + Bs 2*8192 = 25600 floats; SCAN overlay Ys 128x264 = 33792.
// ---------------------------------------------------------------------------
template <int N, int K, bool EPI, bool SCAN>
__global__ void __launch_bounds__(256)
gemm_big(const float* __restrict__ A, const float* __restrict__ BmP,
         float* __restrict__ C, const float* __restrict__ U,
         const float* __restrict__ Dv) {
    constexpr int nk = K / 32;
    constexpr int NJ = N / 8;
    extern __shared__ float sm[];
    float* As = sm;                 // 2 stages * 4608
    float* Bs = sm + 2 * 4608;      // 2 stages * 8192

    const int tid  = threadIdx.x;
    const int lane = tid & 31, warp = tid >> 5;
    const int g = lane >> 2, t = lane & 3;
    const int wr = (warp & 1) * 64;         // warp m-offset
    const int wc = (warp >> 1) * 64;        // warp n-offset
    const int jw = wc >> 3;                 // 8*(warp>>1)
    const int m0 = blockIdx.y * 128, n0 = blockIdx.x * 256;
    const int j0 = n0 >> 3;

    float acc[4][8][4];
#pragma unroll
    for (int i = 0; i < 4; i++)
#pragma unroll
        for (int j = 0; j < 8; j++)
#pragma unroll
            for (int q = 0; q < 4; q++) acc[i][j][q] = 0.0f;

    float4 aReg[4];

    auto ldgA = [&](int kt) {
#pragma unroll
        for (int i = 0; i < 4; i++) {
            int idx = i * 256 + tid;
            int m = idx >> 3, c4 = idx & 7;
            aReg[i] = *reinterpret_cast<const float4*>(
                A + (size_t)(m0 + m) * K + kt * 32 + c4 * 4);
        }
    };
    auto stsA = [&](int s) {
#pragma unroll
        for (int i = 0; i < 4; i++) {
            int idx = i * 256 + tid;
            int m = idx >> 3, c4 = idx & 7;
            float4 v = aReg[i];
            v.x = tf32_rna(v.x); v.y = tf32_rna(v.y);
            v.z = tf32_rna(v.z); v.w = tf32_rna(v.w);
            *reinterpret_cast<float4*>(As + s * 4608 + m * 36 + c4 * 4) = v;
        }
    };
    auto ldB = [&](int s, int kt) {
#pragma unroll
        for (int q = 0; q < 8; q++) {
            int idx = q * 256 + tid;            // 0..2047 float4s
            int kk = idx >> 9;
            int rem = idx & 511;
            int j = rem >> 4, f4 = rem & 15;
            cp_async16(Bs + s * 8192 + (kk * 32 + j) * 64 + f4 * 4,
                       BmP + ((size_t)((kt * 4 + kk) * NJ + j0 + j)) * 64 + f4 * 4);
        }
        asm volatile("cp.async.commit_group;\n" ::);
    };

    // prologue
    ldB(0, 0);
    ldgA(0); stsA(0);
    asm volatile("cp.async.wait_group 0;\n" ::);
    __syncthreads();

    for (int kt = 0; kt < nk; kt++) {
        int s = kt & 1;
        bool more = (kt + 1 < nk);
        if (more) { ldB(s ^ 1, kt + 1); ldgA(kt + 1); }

        const float* Asb = As + s * 4608;
        const float* Bsb = Bs + s * 8192;
#pragma unroll
        for (int kk = 0; kk < 4; kk++) {
            uint32_t af[4][4];
#pragma unroll
            for (int mt = 0; mt < 4; mt++) {
                int row = wr + mt * 16 + g;
                int col = kk * 8 + t;
                af[mt][0] = __float_as_uint(Asb[row * 36 + col]);
                af[mt][1] = __float_as_uint(Asb[(row + 8) * 36 + col]);
                af[mt][2] = __float_as_uint(Asb[row * 36 + col + 4]);
                af[mt][3] = __float_as_uint(Asb[(row + 8) * 36 + col + 4]);
            }
            uint32_t bf[8][2];
#pragma unroll
            for (int nt = 0; nt < 8; nt++) {
                const float2 v = *reinterpret_cast<const float2*>(
                    Bsb + (kk * 32 + jw + nt) * 64 + lane * 2);
                bf[nt][0] = __float_as_uint(v.x);
                bf[nt][1] = __float_as_uint(v.y);
            }
#pragma unroll
            for (int mt = 0; mt < 4; mt++)
#pragma unroll
                for (int nt = 0; nt < 8; nt++)
                    mma_tf32_v(acc[mt][nt], af[mt], bf[nt]);
        }
        if (more) {
            stsA(s ^ 1);
            asm volatile("cp.async.wait_group 0;\n" ::);
        }
        __syncthreads();
    }

    if (!SCAN) {
        // epilogue: (+ D*u) and write out
#pragma unroll
        for (int mt = 0; mt < 4; mt++) {
#pragma unroll
            for (int nt = 0; nt < 8; nt++) {
                int r0 = m0 + wr + mt * 16 + g;
                int cc = n0 + wc + nt * 8 + 2 * t;
                float v0 = acc[mt][nt][0], v1 = acc[mt][nt][1];
                float v2 = acc[mt][nt][2], v3 = acc[mt][nt][3];
                if (EPI) {
                    float d0 = Dv[cc], d1 = Dv[cc + 1];
                    v0 = fmaf(d0, U[(size_t)r0 * 256 + cc],     v0);
                    v1 = fmaf(d1, U[(size_t)r0 * 256 + cc + 1], v1);
                    v2 = fmaf(d0, U[(size_t)(r0 + 8) * 256 + cc],     v2);
                    v3 = fmaf(d1, U[(size_t)(r0 + 8) * 256 + cc + 1], v3);
                }
                *reinterpret_cast<float2*>(C + (size_t)r0 * N + cc) = make_float2(v0, v1);
                *reinterpret_cast<float2*>(C + (size_t)(r0 + 8) * N + cc) = make_float2(v2, v3);
            }
        }
    } else {
        // epilogue: write f to gmem AND stage tile (128 x 256, stride 264)
        float* Ys = sm;
#pragma unroll
        for (int mt = 0; mt < 4; mt++) {
#pragma unroll
            for (int nt = 0; nt < 8; nt++) {
                int rl = wr + mt * 16 + g;
                int ccl = wc + nt * 8 + 2 * t;
                int r0 = m0 + rl;
                float2 v01 = make_float2(acc[mt][nt][0], acc[mt][nt][1]);
                float2 v23 = make_float2(acc[mt][nt][2], acc[mt][nt][3]);
                *reinterpret_cast<float2*>(C + (size_t)r0 * N + n0 + ccl) = v01;
                *reinterpret_cast<float2*>(C + (size_t)(r0 + 8) * N + n0 + ccl) = v23;
                *reinterpret_cast<float2*>(Ys + rl * 264 + ccl) = v01;
                *reinterpret_cast<float2*>(Ys + (rl + 8) * 264 + ccl) = v23;
            }
        }
        __syncthreads();

        // local scan: thread -> col tid (0..255), chunks 0 and 1, zero init
        {
            int ng = n0 + tid;
            int p = ng >> 1, c = ng & 1;
            float m11 = g_m11[p], m12 = g_m12[p], m21 = g_dts[p];
            int b = m0 >> 12;
            int chb = (m0 & 4095) >> 6;
#pragma unroll
            for (int chunk = 0; chunk < 2; chunk++) {
                float x1 = 0.0f, x2 = 0.0f;
                const float* base = Ys + (chunk * 64) * 264 + tid;
#pragma unroll 8
                for (int j = 0; j < CLEN; j++) {
                    float fv = base[j * 264];
                    float n1 = fmaf(m11, x1, fmaf(m12, x2, fv));
                    float n2 = fmaf(m21, x1, x2);
                    x1 = n1; x2 = n2;
                }
                float* cfp = g_cf + ((size_t)(b * 256 + p) * 64 + chb + chunk) * 4;
                cfp[c]     = x1;
                cfp[2 + c] = x2;
            }
        }
    }
}

// ---------------------------------------------------------------------------
// Scan phase 2: warp-parallel cross-chunk combine (Kogge-Stone over 32 lanes)
// ---------------------------------------------------------------------------
__global__ void __launch_bounds__(256) scan_combine() {
    const unsigned FULL = 0xFFFFFFFFu;
    int wg = blockIdx.x * 8 + (threadIdx.x >> 5);   // 0..2047
    int lane = threadIdx.x & 31;
    int b = wg >> 8, p = wg & 255;

    float m11 = g_m11[p], m12 = g_m12[p], m21 = g_dts[p];
    float pa = m11, pb = m12, pc = m21, pd = 1.0f;
#pragma unroll
    for (int i = 0; i < 6; i++) {
        float na = fmaf(pa, pa, pb * pc);
        float nb = fmaf(pa, pb, pb * pd);
        float nc = fmaf(pc, pa, pd * pc);
        float nd = fmaf(pc, pb, pd * pd);
        pa = na; pb = nb; pc = nc; pd = nd;
    }

    const float4* cf = reinterpret_cast<const float4*>(g_cf) + (size_t)(b * 256 + p) * 64;
    float4 v0 = cf[2 * lane];
    float4 v1 = cf[2 * lane + 1];

    float w1r = fmaf(pa, v0.x, fmaf(pb, v0.z, v1.x));
    float w1i = fmaf(pa, v0.y, fmaf(pb, v0.w, v1.y));
    float w2r = fmaf(pc, v0.x, fmaf(pd, v0.z, v1.z));
    float w2i = fmaf(pc, v0.y, fmaf(pd, v0.w, v1.w));
    float ma = fmaf(pa, pa, pb * pc), mb = fmaf(pa, pb, pb * pd);
    float mc = fmaf(pc, pa, pd * pc), md = fmaf(pc, pb, pd * pd);

#pragma unroll
    for (int d = 1; d < 32; d <<= 1) {
        float oa = __shfl_up_sync(FULL, ma, d);
        float ob = __shfl_up_sync(FULL, mb, d);
        float oc = __shfl_up_sync(FULL, mc, d);
        float od = __shfl_up_sync(FULL, md, d);
        float o1r = __shfl_up_sync(FULL, w1r, d);
        float o1i = __shfl_up_sync(FULL, w1i, d);
        float o2r = __shfl_up_sync(FULL, w2r, d);
        float o2i = __shfl_up_sync(FULL, w2i, d);
        if (lane >= d) {
            w1r = fmaf(ma, o1r, fmaf(mb, o2r, w1r));
            w1i = fmaf(ma, o1i, fmaf(mb, o2i, w1i));
            w2r = fmaf(mc, o1r, fmaf(md, o2r, w2r));
            w2i = fmaf(mc, o1i, fmaf(md, o2i, w2i));
            float na = fmaf(ma, oa, mb * oc), nb = fmaf(ma, ob, mb * od);
            float nc = fmaf(mc, oa, md * oc), nd = fmaf(mc, ob, md * od);
            ma = na; mb = nb; mc = nc; md = nd;
        }
    }

    float e1r = __shfl_up_sync(FULL, w1r, 1);
    float e1i = __shfl_up_sync(FULL, w1i, 1);
    float e2r = __shfl_up_sync(FULL, w2r, 1);
    float e2i = __shfl_up_sync(FULL, w2i, 1);
    if (lane == 0) { e1r = e1i = e2r = e2i = 0.0f; }

    float4* gi = reinterpret_cast<float4*>(g_init) + (size_t)(b * 256 + p) * 64;
    gi[2 * lane] = make_float4(e1r, e1i, e2r, e2i);
    gi[2 * lane + 1] = make_float4(
        fmaf(pa, e1r, fmaf(pb, e2r, v0.x)),
        fmaf(pa, e1i, fmaf(pb, e2i, v0.y)),
        fmaf(pc, e1r, fmaf(pd, e2r, v0.z)),
        fmaf(pc, e1i, fmaf(pd, e2i, v0.w)));
}

// ---------------------------------------------------------------------------
// Scan phase 3: re-scan each chunk from corrected init, write ys (raw x2)
// ---------------------------------------------------------------------------
__global__ void scan_final() {
    int b = blockIdx.x >> 6;
    int ch = blockIdx.x & 63;
    int p = threadIdx.x;
    float m11 = g_m11[p], m12 = g_m12[p], m21 = g_dts[p];
    float4 iv = reinterpret_cast<const float4*>(g_init)[(b * 256 + p) * 64 + ch];
    float x1r = iv.x, x1i = iv.y, x2r = iv.z, x2i = iv.w;
    const float2* f = reinterpret_cast<const float2*>(g_f)
                      + ((size_t)(b * Lc + ch * CLEN)) * 256 + p;
    float2* ys = reinterpret_cast<float2*>(g_ys)
                 + ((size_t)(b * Lc + ch * CLEN)) * 256 + p;
#pragma unroll 8
    for (int j = 0; j < CLEN; j++) {
        float2 fv = f[(size_t)j * 256];
        float n1r = fmaf(m11, x1r, fmaf(m12, x2r, fv.x));
        float n2r = fmaf(m21, x1r, x2r);
        float n1i = fmaf(m11, x1i, fmaf(m12, x2i, fv.y));
        float n2i = fmaf(m21, x1i, x2i);
        x1r = n1r; x2r = n2r; x1i = n1i; x2i = n2i;
        ys[(size_t)j * 256] = make_float2(x2r, x2i);
    }
}

// ---------------------------------------------------------------------------
extern "C" void kernel_launch(void* const* d_in, const int* in_sizes, int n_in,
                              void* d_out, int out_size) {
    const float* u  = (const float*)d_in[0];
    const float* Ad = (const float*)d_in[1];
    const float* Gd = (const float*)d_in[2];
    const float* dt = (const float*)d_in[3];
    const float* Bm = (const float*)d_in[4];
    const float* Cm = (const float*)d_in[5];
    const float* Dv = (const float*)d_in[6];
    float* out = (float*)d_out;

    float *fptr, *ysptr, *bop, *cop;
    cudaGetSymbolAddress((void**)&fptr,  g_f);
    cudaGetSymbolAddress((void**)&ysptr, g_ys);
    cudaGetSymbolAddress((void**)&bop,   g_BopP);
    cudaGetSymbolAddress((void**)&cop,   g_CopP);

    const int smem1 = 33792 * 4;   // 135168 (Ys overlay dominates)
    const int smem2 = 25600 * 4;   // 102400
    cudaFuncSetAttribute(gemm_big<512, 256, false, true>,
                         cudaFuncAttributeMaxDynamicSharedMemorySize, smem1);
    cudaFuncSetAttribute(gemm_big<256, 512, true, false>,
                         cudaFuncAttributeMaxDynamicSharedMemorySize, smem2);

    prep_kernel<<<256, 512>>>(Ad, Gd, dt, Bm, Cm);

    // GEMM1 + fused local scan: f = u @ Bop, chunk-final states -> g_cf
    gemm_big<512, 256, false, true><<<dim3(2, 256), 256, smem1>>>(
        u, bop, fptr, nullptr, nullptr);

    scan_combine<<<256, 256>>>();

    // final scan: ys = scan(f) with corrected inits
    scan_final<<<Bc * NCHUNK, 256>>>();

    // GEMM2: out = ys @ Cop + D*u
    gemm_big<256, 512, true, false><<<dim3(1, 256), 256, smem2>>>(
        ysptr, cop, out, u, Dv);
}

// round 11
// speedup vs baseline: 1.3258x; 1.3258x over previous
#include <cuda_runtime.h>
#include <cuda_fp16.h>
#include <cstdint>

// Problem constants
constexpr int Bc = 8, Lc = 4096;
constexpr int Mrows = Bc * Lc;          // 32768
constexpr int NCHUNK = 64, CLEN = 64;   // 64 chunks of 64 steps

// Scratch (static device arrays -- no allocation allowed)
__device__ float  g_f [(size_t)Mrows * 512];  // f = dt_s*Bu : [bl][2p+c]
__device__ float  g_ys[(size_t)Mrows * 512];  // ys, same layout
__device__ __half g_BopH[512 * 256];          // GEMM1 B, [n=2p+c][k=h]
__device__ __half g_CopH[256 * 512];          // GEMM2 B, [n=h][k=2p+c]
__device__ float  g_m11[256], g_m12[256], g_dts[256];
__device__ float  g_cf  [Bc * 256 * NCHUNK * 4]; // [b][p][ch] float4
__device__ float  g_init[Bc * 256 * NCHUNK * 4];

__device__ __forceinline__ void cp_async16(void* smem, const void* gmem) {
    uint32_t s = (uint32_t)__cvta_generic_to_shared(smem);
    asm volatile("cp.async.ca.shared.global [%0], [%1], 16;\n" :: "r"(s), "l"(gmem));
}

__device__ __forceinline__ void mma_f16(float c[4], const uint32_t a[4], const uint32_t b[2]) {
    asm volatile(
        "mma.sync.aligned.m16n8k16.row.col.f32.f16.f16.f32 "
        "{%0,%1,%2,%3}, {%4,%5,%6,%7}, {%8,%9}, {%0,%1,%2,%3};\n"
        : "+f"(c[0]), "+f"(c[1]), "+f"(c[2]), "+f"(c[3])
        : "r"(a[0]), "r"(a[1]), "r"(a[2]), "r"(a[3]), "r"(b[0]), "r"(b[1]));
}

// ---------------------------------------------------------------------------
// Prep: per-p recurrence params + fp16 operand matrices (B stored [n][k])
// Interleaved layout n = 2p + c  (c=0 re, c=1 im)
// ---------------------------------------------------------------------------
__global__ void prep_kernel(const float* __restrict__ Ad, const float* __restrict__ Gd,
                            const float* __restrict__ dt, const float* __restrict__ Bm,
                            const float* __restrict__ Cm) {
    int h = blockIdx.x;          // 0..255
    int n = threadIdx.x;         // 0..511
    int p = n >> 1;
    int c = n & 1;
    float dts = 1.0f / (1.0f + expf(-dt[p]));
    float G = fmaxf(Gd[p], dts * Ad[p]);
    float A = fmaxf(Ad[p], 0.25f * G * G);

    // GEMM1 B: [n][k=h]
    g_BopH[n * 256 + h] = __float2half(dts * Bm[p * 512 + h * 2 + c]);
    // GEMM2 B: [n=h][k=2p+c]
    float cv = Cm[h * 512 + p * 2 + c];
    g_CopH[h * 512 + n] = __float2half(c ? -cv : cv);

    if (h == 0 && c == 0) {
        g_m11[p] = 1.0f - dts * G;
        g_m12[p] = -dts * A;
        g_dts[p] = dts;          // m21; m22 == 1
    }
}

// ---------------------------------------------------------------------------
// fp16 GEMM: C[M x N] = A[M x K] @ B  (B fp16 gmem [N][K])
// Block tile 128x128x32, 8 warps (2m x 4n), warp tile 64x32, m16n8k16 mma.
// A: float gmem -> fp16 smem [128][40] (conflict-free frag loads).
// B: fp16 gmem rows -> cp.async -> smem [128][40].
// SCAN: gemm1 epilogue stages f tile (128x132 fp32 overlay) + local scans.
// EPI : gemm2 epilogue adds D*u.
// ---------------------------------------------------------------------------
template <int N, int K, bool EPI, bool SCAN>
__global__ void __launch_bounds__(256, 2)
gemm_f16(const float* __restrict__ A, const __half* __restrict__ BmH,
         float* __restrict__ C, const float* __restrict__ U,
         const float* __restrict__ Dv) {
    constexpr int nk = K / 32;
    extern __shared__ __half smh[];
    __half* As = smh;                 // 2 stages * 128*40
    __half* Bs = smh + 2 * 5120;      // 2 stages * 128*40

    const int tid  = threadIdx.x;
    const int lane = tid & 31, warp = tid >> 5;
    const int g = lane >> 2, t = lane & 3;
    const int wr = (warp & 1) * 64, wc = (warp >> 1) * 32;
    const int m0 = blockIdx.y * 128, n0 = blockIdx.x * 128;

    float acc[4][4][4];
#pragma unroll
    for (int i = 0; i < 4; i++)
#pragma unroll
        for (int j = 0; j < 4; j++)
#pragma unroll
            for (int q = 0; q < 4; q++) acc[i][j][q] = 0.0f;

    float4 aReg[4];

    auto ldgA = [&](int kt) {
#pragma unroll
        for (int i = 0; i < 4; i++) {
            int idx = i * 256 + tid;
            int m = idx >> 3, c4 = idx & 7;
            aReg[i] = *reinterpret_cast<const float4*>(
                A + (size_t)(m0 + m) * K + kt * 32 + c4 * 4);
        }
    };
    auto stsA = [&](int s) {
#pragma unroll
        for (int i = 0; i < 4; i++) {
            int idx = i * 256 + tid;
            int m = idx >> 3, c4 = idx & 7;
            float4 v = aReg[i];
            __half2 h01 = __floats2half2_rn(v.x, v.y);
            __half2 h23 = __floats2half2_rn(v.z, v.w);
            uint2 pk;
            pk.x = *reinterpret_cast<uint32_t*>(&h01);
            pk.y = *reinterpret_cast<uint32_t*>(&h23);
            *reinterpret_cast<uint2*>(As + s * 5120 + m * 40 + c4 * 4) = pk;
        }
    };
    auto ldB = [&](int s, int kt) {
#pragma unroll
        for (int q = 0; q < 2; q++) {
            int idx = q * 256 + tid;       // 0..511 16B chunks
            int row = idx >> 2, c = idx & 3;
            cp_async16(Bs + s * 5120 + row * 40 + c * 8,
                       BmH + (size_t)(n0 + row) * K + kt * 32 + c * 8);
        }
        asm volatile("cp.async.commit_group;\n" ::);
    };

    // prologue
    ldB(0, 0);
    ldgA(0); stsA(0);
    asm volatile("cp.async.wait_group 0;\n" ::);
    __syncthreads();

    for (int kt = 0; kt < nk; kt++) {
        int s = kt & 1;
        bool more = (kt + 1 < nk);
        if (more) { ldB(s ^ 1, kt + 1); ldgA(kt + 1); }

        const __half* Asb = As + s * 5120;
        const __half* Bsb = Bs + s * 5120;
#pragma unroll
        for (int kk = 0; kk < 2; kk++) {           // two k16 steps per 32-k slab
            uint32_t af[4][4];
#pragma unroll
            for (int mt = 0; mt < 4; mt++) {
                int row = wr + mt * 16 + g;
                int col = kk * 16 + 2 * t;
                af[mt][0] = *reinterpret_cast<const uint32_t*>(Asb + row * 40 + col);
                af[mt][1] = *reinterpret_cast<const uint32_t*>(Asb + (row + 8) * 40 + col);
                af[mt][2] = *reinterpret_cast<const uint32_t*>(Asb + row * 40 + col + 8);
                af[mt][3] = *reinterpret_cast<const uint32_t*>(Asb + (row + 8) * 40 + col + 8);
            }
            uint32_t bf[4][2];
#pragma unroll
            for (int nt = 0; nt < 4; nt++) {
                int nl = wc + nt * 8 + g;
                int col = kk * 16 + 2 * t;
                bf[nt][0] = *reinterpret_cast<const uint32_t*>(Bsb + nl * 40 + col);
                bf[nt][1] = *reinterpret_cast<const uint32_t*>(Bsb + nl * 40 + col + 8);
            }
#pragma unroll
            for (int mt = 0; mt < 4; mt++)
#pragma unroll
                for (int nt = 0; nt < 4; nt++)
                    mma_f16(acc[mt][nt], af[mt], bf[nt]);
        }
        if (more) {
            stsA(s ^ 1);
            asm volatile("cp.async.wait_group 0;\n" ::);
        }
        __syncthreads();
    }

    if (!SCAN) {
        // epilogue: (+ D*u) write out
#pragma unroll
        for (int mt = 0; mt < 4; mt++) {
#pragma unroll
            for (int nt = 0; nt < 4; nt++) {
                int r0 = m0 + wr + mt * 16 + g;
                int cc = n0 + wc + nt * 8 + 2 * t;
                float v0 = acc[mt][nt][0], v1 = acc[mt][nt][1];
                float v2 = acc[mt][nt][2], v3 = acc[mt][nt][3];
                if (EPI) {
                    float d0 = Dv[cc], d1 = Dv[cc + 1];
                    v0 = fmaf(d0, U[(size_t)r0 * 256 + cc],     v0);
                    v1 = fmaf(d1, U[(size_t)r0 * 256 + cc + 1], v1);
                    v2 = fmaf(d0, U[(size_t)(r0 + 8) * 256 + cc],     v2);
                    v3 = fmaf(d1, U[(size_t)(r0 + 8) * 256 + cc + 1], v3);
                }
                *reinterpret_cast<float2*>(C + (size_t)r0 * N + cc) = make_float2(v0, v1);
                *reinterpret_cast<float2*>(C + (size_t)(r0 + 8) * N + cc) = make_float2(v2, v3);
            }
        }
    } else {
        // epilogue: write f AND stage tile (fp32 overlay 128x132) for local scan
        float* Ys = reinterpret_cast<float*>(smh);
#pragma unroll
        for (int mt = 0; mt < 4; mt++) {
#pragma unroll
            for (int nt = 0; nt < 4; nt++) {
                int rl = wr + mt * 16 + g;
                int ccl = wc + nt * 8 + 2 * t;
                int r0 = m0 + rl;
                float2 v01 = make_float2(acc[mt][nt][0], acc[mt][nt][1]);
                float2 v23 = make_float2(acc[mt][nt][2], acc[mt][nt][3]);
                *reinterpret_cast<float2*>(C + (size_t)r0 * N + n0 + ccl) = v01;
                *reinterpret_cast<float2*>(C + (size_t)(r0 + 8) * N + n0 + ccl) = v23;
                *reinterpret_cast<float2*>(Ys + rl * 132 + ccl) = v01;
                *reinterpret_cast<float2*>(Ys + (rl + 8) * 132 + ccl) = v23;
            }
        }
        __syncthreads();

        // local scan: thread -> (col 0..127, chunk 0..1), zero init
        {
            int col = tid & 127, chunk = tid >> 7;
            int ng = n0 + col;
            int p = ng >> 1, c = ng & 1;
            float m11 = g_m11[p], m12 = g_m12[p], m21 = g_dts[p];
            float x1 = 0.0f, x2 = 0.0f;
            const float* base = Ys + (chunk * 64) * 132 + col;
#pragma unroll 8
            for (int j = 0; j < CLEN; j++) {
                float fv = base[j * 132];
                float n1 = fmaf(m11, x1, fmaf(m12, x2, fv));
                float n2 = fmaf(m21, x1, x2);
                x1 = n1; x2 = n2;
            }
            int b = m0 >> 12;
            int ch = ((m0 & 4095) >> 6) + chunk;
            float* cfp = g_cf + ((size_t)(b * 256 + p) * 64 + ch) * 4;
            cfp[c]     = x1;
            cfp[2 + c] = x2;
        }
    }
}

// ---------------------------------------------------------------------------
// Scan phase 2: warp-parallel cross-chunk combine (Kogge-Stone over 32 lanes)
// ---------------------------------------------------------------------------
__global__ void __launch_bounds__(256) scan_combine() {
    const unsigned FULL = 0xFFFFFFFFu;
    int wg = blockIdx.x * 8 + (threadIdx.x >> 5);   // 0..2047
    int lane = threadIdx.x & 31;
    int b = wg >> 8, p = wg & 255;

    float m11 = g_m11[p], m12 = g_m12[p], m21 = g_dts[p];
    float pa = m11, pb = m12, pc = m21, pd = 1.0f;
#pragma unroll
    for (int i = 0; i < 6; i++) {
        float na = fmaf(pa, pa, pb * pc);
        float nb = fmaf(pa, pb, pb * pd);
        float nc = fmaf(pc, pa, pd * pc);
        float nd = fmaf(pc, pb, pd * pd);
        pa = na; pb = nb; pc = nc; pd = nd;
    }

    const float4* cf = reinterpret_cast<const float4*>(g_cf) + (size_t)(b * 256 + p) * 64;
    float4 v0 = cf[2 * lane];
    float4 v1 = cf[2 * lane + 1];

    float w1r = fmaf(pa, v0.x, fmaf(pb, v0.z, v1.x));
    float w1i = fmaf(pa, v0.y, fmaf(pb, v0.w, v1.y));
    float w2r = fmaf(pc, v0.x, fmaf(pd, v0.z, v1.z));
    float w2i = fmaf(pc, v0.y, fmaf(pd, v0.w, v1.w));
    float ma = fmaf(pa, pa, pb * pc), mb = fmaf(pa, pb, pb * pd);
    float mc = fmaf(pc, pa, pd * pc), md = fmaf(pc, pb, pd * pd);

#pragma unroll
    for (int d = 1; d < 32; d <<= 1) {
        float oa = __shfl_up_sync(FULL, ma, d);
        float ob = __shfl_up_sync(FULL, mb, d);
        float oc = __shfl_up_sync(FULL, mc, d);
        float od = __shfl_up_sync(FULL, md, d);
        float o1r = __shfl_up_sync(FULL, w1r, d);
        float o1i = __shfl_up_sync(FULL, w1i, d);
        float o2r = __shfl_up_sync(FULL, w2r, d);
        float o2i = __shfl_up_sync(FULL, w2i, d);
        if (lane >= d) {
            w1r = fmaf(ma, o1r, fmaf(mb, o2r, w1r));
            w1i = fmaf(ma, o1i, fmaf(mb, o2i, w1i));
            w2r = fmaf(mc, o1r, fmaf(md, o2r, w2r));
            w2i = fmaf(mc, o1i, fmaf(md, o2i, w2i));
            float na = fmaf(ma, oa, mb * oc), nb = fmaf(ma, ob, mb * od);
            float nc = fmaf(mc, oa, md * oc), nd = fmaf(mc, ob, md * od);
            ma = na; mb = nb; mc = nc; md = nd;
        }
    }

    float e1r = __shfl_up_sync(FULL, w1r, 1);
    float e1i = __shfl_up_sync(FULL, w1i, 1);
    float e2r = __shfl_up_sync(FULL, w2r, 1);
    float e2i = __shfl_up_sync(FULL, w2i, 1);
    if (lane == 0) { e1r = e1i = e2r = e2i = 0.0f; }

    float4* gi = reinterpret_cast<float4*>(g_init) + (size_t)(b * 256 + p) * 64;
    gi[2 * lane] = make_float4(e1r, e1i, e2r, e2i);
    gi[2 * lane + 1] = make_float4(
        fmaf(pa, e1r, fmaf(pb, e2r, v0.x)),
        fmaf(pa, e1i, fmaf(pb, e2i, v0.y)),
        fmaf(pc, e1r, fmaf(pd, e2r, v0.z)),
        fmaf(pc, e1i, fmaf(pd, e2i, v0.w)));
}

// ---------------------------------------------------------------------------
// Scan phase 3: re-scan each chunk from corrected init, write ys (raw x2)
// ---------------------------------------------------------------------------
__global__ void scan_final() {
    int b = blockIdx.x >> 6;
    int ch = blockIdx.x & 63;
    int p = threadIdx.x;
    float m11 = g_m11[p], m12 = g_m12[p], m21 = g_dts[p];
    float4 iv = reinterpret_cast<const float4*>(g_init)[(b * 256 + p) * 64 + ch];
    float x1r = iv.x, x1i = iv.y, x2r = iv.z, x2i = iv.w;
    const float2* f = reinterpret_cast<const float2*>(g_f)
                      + ((size_t)(b * Lc + ch * CLEN)) * 256 + p;
    float2* ys = reinterpret_cast<float2*>(g_ys)
                 + ((size_t)(b * Lc + ch * CLEN)) * 256 + p;
#pragma unroll 8
    for (int j = 0; j < CLEN; j++) {
        float2 fv = f[(size_t)j * 256];
        float n1r = fmaf(m11, x1r, fmaf(m12, x2r, fv.x));
        float n2r = fmaf(m21, x1r, x2r);
        float n1i = fmaf(m11, x1i, fmaf(m12, x2i, fv.y));
        float n2i = fmaf(m21, x1i, x2i);
        x1r = n1r; x2r = n2r; x1i = n1i; x2i = n2i;
        ys[(size_t)j * 256] = make_float2(x2r, x2i);
    }
}

// ---------------------------------------------------------------------------
extern "C" void kernel_launch(void* const* d_in, const int* in_sizes, int n_in,
                              void* d_out, int out_size) {
    const float* u  = (const float*)d_in[0];
    const float* Ad = (const float*)d_in[1];
    const float* Gd = (const float*)d_in[2];
    const float* dt = (const float*)d_in[3];
    const float* Bm = (const float*)d_in[4];
    const float* Cm = (const float*)d_in[5];
    const float* Dv = (const float*)d_in[6];
    float* out = (float*)d_out;

    float *fptr, *ysptr;
    __half *bop, *cop;
    cudaGetSymbolAddress((void**)&fptr,  g_f);
    cudaGetSymbolAddress((void**)&ysptr, g_ys);
    cudaGetSymbolAddress((void**)&bop,   g_BopH);
    cudaGetSymbolAddress((void**)&cop,   g_CopH);

    const int smem1 = 128 * 132 * 4;        // 67584 (fp32 scan overlay dominates)
    const int smem2 = 4 * 5120 * 2;         // 40960 (fp16 GEMM tiles)
    cudaFuncSetAttribute(gemm_f16<512, 256, false, true>,
                         cudaFuncAttributeMaxDynamicSharedMemorySize, smem1);
    cudaFuncSetAttribute(gemm_f16<256, 512, true, false>,
                         cudaFuncAttributeMaxDynamicSharedMemorySize, smem2);

    prep_kernel<<<256, 512>>>(Ad, Gd, dt, Bm, Cm);

    // GEMM1 + fused local scan: f = u @ Bop^T, chunk-final states -> g_cf
    gemm_f16<512, 256, false, true><<<dim3(4, 256), 256, smem1>>>(
        u, bop, fptr, nullptr, nullptr);

    scan_combine<<<256, 256>>>();

    // final scan: ys = scan(f) with corrected inits
    scan_final<<<Bc * NCHUNK, 256>>>();

    // GEMM2: out = ys @ Cop^T + D*u
    gemm_f16<256, 512, true, false><<<dim3(2, 256), 256, smem2>>>(
        ysptr, cop, out, u, Dv);
}

// round 12
// speedup vs baseline: 1.4489x; 1.0928x over previous
#include <cuda_runtime.h>
#include <cuda_fp16.h>
#include <cstdint>

// Problem constants
constexpr int Bc = 8, Lc = 4096;
constexpr int Mrows = Bc * Lc;          // 32768
constexpr int NCHUNK = 64, CLEN = 64;   // 64 chunks of 64 steps

// Scratch (static device arrays -- no allocation allowed)
__device__ __half g_fh [(size_t)Mrows * 512]; // f  (fp16): [bl][2p+c]
__device__ __half g_ysh[(size_t)Mrows * 512]; // ys (fp16), same layout
__device__ __half g_BopH[512 * 256];          // GEMM1 B, [n=2p+c][k=h]
__device__ __half g_CopH[256 * 512];          // GEMM2 B, [n=h][k=2p+c]
__device__ float  g_m11[256], g_m12[256], g_dts[256];
__device__ float  g_cf  [Bc * 256 * NCHUNK * 4]; // [b][p][ch] float4
__device__ float  g_init[Bc * 256 * NCHUNK * 4];

__device__ __forceinline__ void cp_async16(void* smem, const void* gmem) {
    uint32_t s = (uint32_t)__cvta_generic_to_shared(smem);
    asm volatile("cp.async.ca.shared.global [%0], [%1], 16;\n" :: "r"(s), "l"(gmem));
}

__device__ __forceinline__ void mma_f16(float c[4], const uint32_t a[4], const uint32_t b[2]) {
    asm volatile(
        "mma.sync.aligned.m16n8k16.row.col.f32.f16.f16.f32 "
        "{%0,%1,%2,%3}, {%4,%5,%6,%7}, {%8,%9}, {%0,%1,%2,%3};\n"
        : "+f"(c[0]), "+f"(c[1]), "+f"(c[2]), "+f"(c[3])
        : "r"(a[0]), "r"(a[1]), "r"(a[2]), "r"(a[3]), "r"(b[0]), "r"(b[1]));
}

// ---------------------------------------------------------------------------
// Prep: per-p recurrence params + fp16 operand matrices (B stored [n][k])
// ---------------------------------------------------------------------------
__global__ void prep_kernel(const float* __restrict__ Ad, const float* __restrict__ Gd,
                            const float* __restrict__ dt, const float* __restrict__ Bm,
                            const float* __restrict__ Cm) {
    int h = blockIdx.x;          // 0..255
    int n = threadIdx.x;         // 0..511
    int p = n >> 1;
    int c = n & 1;
    float dts = 1.0f / (1.0f + expf(-dt[p]));
    float G = fmaxf(Gd[p], dts * Ad[p]);
    float A = fmaxf(Ad[p], 0.25f * G * G);

    g_BopH[n * 256 + h] = __float2half(dts * Bm[p * 512 + h * 2 + c]);
    float cv = Cm[h * 512 + p * 2 + c];
    g_CopH[h * 512 + n] = __float2half(c ? -cv : cv);

    if (h == 0 && c == 0) {
        g_m11[p] = 1.0f - dts * G;
        g_m12[p] = -dts * A;
        g_dts[p] = dts;          // m21; m22 == 1
    }
}

// ---------------------------------------------------------------------------
// GEMM1 (+ fused local scan): f = u @ Bop^T  (M=32768, N=512, K=256)
// fp16 mma; A = u (fp32 gmem -> fp16 smem); B fp16 cp.async.
// Epilogue: write f as fp16, stage double-rounded values, run local scans.
// ---------------------------------------------------------------------------
__global__ void __launch_bounds__(256, 2)
gemm1_f16(const float* __restrict__ A, const __half* __restrict__ BmH,
          __half* __restrict__ F) {
    constexpr int N = 512, K = 256, nk = K / 32;
    extern __shared__ __half smh[];
    __half* As = smh;                 // 2 stages * 128*40
    __half* Bs = smh + 2 * 5120;

    const int tid  = threadIdx.x;
    const int lane = tid & 31, warp = tid >> 5;
    const int g = lane >> 2, t = lane & 3;
    const int wr = (warp & 1) * 64, wc = (warp >> 1) * 32;
    const int m0 = blockIdx.y * 128, n0 = blockIdx.x * 128;

    float acc[4][4][4];
#pragma unroll
    for (int i = 0; i < 4; i++)
#pragma unroll
        for (int j = 0; j < 4; j++)
#pragma unroll
            for (int q = 0; q < 4; q++) acc[i][j][q] = 0.0f;

    float4 aReg[4];

    auto ldgA = [&](int kt) {
#pragma unroll
        for (int i = 0; i < 4; i++) {
            int idx = i * 256 + tid;
            int m = idx >> 3, c4 = idx & 7;
            aReg[i] = *reinterpret_cast<const float4*>(
                A + (size_t)(m0 + m) * K + kt * 32 + c4 * 4);
        }
    };
    auto stsA = [&](int s) {
#pragma unroll
        for (int i = 0; i < 4; i++) {
            int idx = i * 256 + tid;
            int m = idx >> 3, c4 = idx & 7;
            float4 v = aReg[i];
            __half2 h01 = __floats2half2_rn(v.x, v.y);
            __half2 h23 = __floats2half2_rn(v.z, v.w);
            uint2 pk;
            pk.x = *reinterpret_cast<uint32_t*>(&h01);
            pk.y = *reinterpret_cast<uint32_t*>(&h23);
            *reinterpret_cast<uint2*>(As + s * 5120 + m * 40 + c4 * 4) = pk;
        }
    };
    auto ldB = [&](int s, int kt) {
#pragma unroll
        for (int q = 0; q < 2; q++) {
            int idx = q * 256 + tid;
            int row = idx >> 2, c = idx & 3;
            cp_async16(Bs + s * 5120 + row * 40 + c * 8,
                       BmH + (size_t)(n0 + row) * K + kt * 32 + c * 8);
        }
        asm volatile("cp.async.commit_group;\n" ::);
    };

    ldB(0, 0);
    ldgA(0); stsA(0);
    asm volatile("cp.async.wait_group 0;\n" ::);
    __syncthreads();

    for (int kt = 0; kt < nk; kt++) {
        int s = kt & 1;
        bool more = (kt + 1 < nk);
        if (more) { ldB(s ^ 1, kt + 1); ldgA(kt + 1); }

        const __half* Asb = As + s * 5120;
        const __half* Bsb = Bs + s * 5120;
#pragma unroll
        for (int kk = 0; kk < 2; kk++) {
            uint32_t af[4][4];
#pragma unroll
            for (int mt = 0; mt < 4; mt++) {
                int row = wr + mt * 16 + g;
                int col = kk * 16 + 2 * t;
                af[mt][0] = *reinterpret_cast<const uint32_t*>(Asb + row * 40 + col);
                af[mt][1] = *reinterpret_cast<const uint32_t*>(Asb + (row + 8) * 40 + col);
                af[mt][2] = *reinterpret_cast<const uint32_t*>(Asb + row * 40 + col + 8);
                af[mt][3] = *reinterpret_cast<const uint32_t*>(Asb + (row + 8) * 40 + col + 8);
            }
            uint32_t bf[4][2];
#pragma unroll
            for (int nt = 0; nt < 4; nt++) {
                int nl = wc + nt * 8 + g;
                int col = kk * 16 + 2 * t;
                bf[nt][0] = *reinterpret_cast<const uint32_t*>(Bsb + nl * 40 + col);
                bf[nt][1] = *reinterpret_cast<const uint32_t*>(Bsb + nl * 40 + col + 8);
            }
#pragma unroll
            for (int mt = 0; mt < 4; mt++)
#pragma unroll
                for (int nt = 0; nt < 4; nt++)
                    mma_f16(acc[mt][nt], af[mt], bf[nt]);
        }
        if (more) {
            stsA(s ^ 1);
            asm volatile("cp.async.wait_group 0;\n" ::);
        }
        __syncthreads();
    }

    // epilogue: f -> gmem (fp16) AND stage double-rounded values for local scan
    float* Ys = reinterpret_cast<float*>(smh);   // overlay 128 x 132 fp32
#pragma unroll
    for (int mt = 0; mt < 4; mt++) {
#pragma unroll
        for (int nt = 0; nt < 4; nt++) {
            int rl = wr + mt * 16 + g;
            int ccl = wc + nt * 8 + 2 * t;
            int r0 = m0 + rl;
            __half2 h01 = __floats2half2_rn(acc[mt][nt][0], acc[mt][nt][1]);
            __half2 h23 = __floats2half2_rn(acc[mt][nt][2], acc[mt][nt][3]);
            *reinterpret_cast<__half2*>(F + (size_t)r0 * N + n0 + ccl) = h01;
            *reinterpret_cast<__half2*>(F + (size_t)(r0 + 8) * N + n0 + ccl) = h23;
            float2 v01 = __half22float2(h01);
            float2 v23 = __half22float2(h23);
            *reinterpret_cast<float2*>(Ys + rl * 132 + ccl) = v01;
            *reinterpret_cast<float2*>(Ys + (rl + 8) * 132 + ccl) = v23;
        }
    }
    __syncthreads();

    // local scan: thread -> (col 0..127, chunk 0..1), zero init
    {
        int col = tid & 127, chunk = tid >> 7;
        int ng = n0 + col;
        int p = ng >> 1, c = ng & 1;
        float m11 = g_m11[p], m12 = g_m12[p], m21 = g_dts[p];
        float x1 = 0.0f, x2 = 0.0f;
        const float* base = Ys + (chunk * 64) * 132 + col;
#pragma unroll 8
        for (int j = 0; j < CLEN; j++) {
            float fv = base[j * 132];
            float n1 = fmaf(m11, x1, fmaf(m12, x2, fv));
            float n2 = fmaf(m21, x1, x2);
            x1 = n1; x2 = n2;
        }
        int b = m0 >> 12;
        int ch = ((m0 & 4095) >> 6) + chunk;
        float* cfp = g_cf + ((size_t)(b * 256 + p) * 64 + ch) * 4;
        cfp[c]     = x1;
        cfp[2 + c] = x2;
    }
}

// ---------------------------------------------------------------------------
// Scan phase 2: warp-parallel cross-chunk combine (Kogge-Stone over 32 lanes)
// ---------------------------------------------------------------------------
__global__ void __launch_bounds__(256) scan_combine() {
    const unsigned FULL = 0xFFFFFFFFu;
    int wg = blockIdx.x * 8 + (threadIdx.x >> 5);   // 0..2047
    int lane = threadIdx.x & 31;
    int b = wg >> 8, p = wg & 255;

    float m11 = g_m11[p], m12 = g_m12[p], m21 = g_dts[p];
    float pa = m11, pb = m12, pc = m21, pd = 1.0f;
#pragma unroll
    for (int i = 0; i < 6; i++) {
        float na = fmaf(pa, pa, pb * pc);
        float nb = fmaf(pa, pb, pb * pd);
        float nc = fmaf(pc, pa, pd * pc);
        float nd = fmaf(pc, pb, pd * pd);
        pa = na; pb = nb; pc = nc; pd = nd;
    }

    const float4* cf = reinterpret_cast<const float4*>(g_cf) + (size_t)(b * 256 + p) * 64;
    float4 v0 = cf[2 * lane];
    float4 v1 = cf[2 * lane + 1];

    float w1r = fmaf(pa, v0.x, fmaf(pb, v0.z, v1.x));
    float w1i = fmaf(pa, v0.y, fmaf(pb, v0.w, v1.y));
    float w2r = fmaf(pc, v0.x, fmaf(pd, v0.z, v1.z));
    float w2i = fmaf(pc, v0.y, fmaf(pd, v0.w, v1.w));
    float ma = fmaf(pa, pa, pb * pc), mb = fmaf(pa, pb, pb * pd);
    float mc = fmaf(pc, pa, pd * pc), md = fmaf(pc, pb, pd * pd);

#pragma unroll
    for (int d = 1; d < 32; d <<= 1) {
        float oa = __shfl_up_sync(FULL, ma, d);
        float ob = __shfl_up_sync(FULL, mb, d);
        float oc = __shfl_up_sync(FULL, mc, d);
        float od = __shfl_up_sync(FULL, md, d);
        float o1r = __shfl_up_sync(FULL, w1r, d);
        float o1i = __shfl_up_sync(FULL, w1i, d);
        float o2r = __shfl_up_sync(FULL, w2r, d);
        float o2i = __shfl_up_sync(FULL, w2i, d);
        if (lane >= d) {
            w1r = fmaf(ma, o1r, fmaf(mb, o2r, w1r));
            w1i = fmaf(ma, o1i, fmaf(mb, o2i, w1i));
            w2r = fmaf(mc, o1r, fmaf(md, o2r, w2r));
            w2i = fmaf(mc, o1i, fmaf(md, o2i, w2i));
            float na = fmaf(ma, oa, mb * oc), nb = fmaf(ma, ob, mb * od);
            float nc = fmaf(mc, oa, md * oc), nd = fmaf(mc, ob, md * od);
            ma = na; mb = nb; mc = nc; md = nd;
        }
    }

    float e1r = __shfl_up_sync(FULL, w1r, 1);
    float e1i = __shfl_up_sync(FULL, w1i, 1);
    float e2r = __shfl_up_sync(FULL, w2r, 1);
    float e2i = __shfl_up_sync(FULL, w2i, 1);
    if (lane == 0) { e1r = e1i = e2r = e2i = 0.0f; }

    float4* gi = reinterpret_cast<float4*>(g_init) + (size_t)(b * 256 + p) * 64;
    gi[2 * lane] = make_float4(e1r, e1i, e2r, e2i);
    gi[2 * lane + 1] = make_float4(
        fmaf(pa, e1r, fmaf(pb, e2r, v0.x)),
        fmaf(pa, e1i, fmaf(pb, e2i, v0.y)),
        fmaf(pc, e1r, fmaf(pd, e2r, v0.z)),
        fmaf(pc, e1i, fmaf(pd, e2i, v0.w)));
}

// ---------------------------------------------------------------------------
// Scan phase 3: re-scan each chunk from corrected init (fp16 f -> fp16 ys)
// ---------------------------------------------------------------------------
__global__ void scan_final() {
    int b = blockIdx.x >> 6;
    int ch = blockIdx.x & 63;
    int p = threadIdx.x;
    float m11 = g_m11[p], m12 = g_m12[p], m21 = g_dts[p];
    float4 iv = reinterpret_cast<const float4*>(g_init)[(b * 256 + p) * 64 + ch];
    float x1r = iv.x, x1i = iv.y, x2r = iv.z, x2i = iv.w;
    const __half2* f = reinterpret_cast<const __half2*>(g_fh)
                       + ((size_t)(b * Lc + ch * CLEN)) * 256 + p;
    __half2* ys = reinterpret_cast<__half2*>(g_ysh)
                  + ((size_t)(b * Lc + ch * CLEN)) * 256 + p;
#pragma unroll 8
    for (int j = 0; j < CLEN; j++) {
        float2 fv = __half22float2(f[(size_t)j * 256]);
        float n1r = fmaf(m11, x1r, fmaf(m12, x2r, fv.x));
        float n2r = fmaf(m21, x1r, x2r);
        float n1i = fmaf(m11, x1i, fmaf(m12, x2i, fv.y));
        float n2i = fmaf(m21, x1i, x2i);
        x1r = n1r; x2r = n2r; x1i = n1i; x2i = n2i;
        ys[(size_t)j * 256] = __floats2half2_rn(x2r, x2i);
    }
}

// ---------------------------------------------------------------------------
// GEMM2: out = ys @ Cop^T + D*u  (M=32768, N=256, K=512)
// Both operands fp16 in gmem; A and B via cp.async (no register staging).
// ---------------------------------------------------------------------------
__global__ void __launch_bounds__(256, 2)
gemm2_f16(const __half* __restrict__ AH, const __half* __restrict__ BmH,
          float* __restrict__ Out, const float* __restrict__ U,
          const float* __restrict__ Dv) {
    constexpr int N = 256, K = 512, nk = K / 32;
    extern __shared__ __half smh[];
    __half* As = smh;                 // 2 stages * 128*40
    __half* Bs = smh + 2 * 5120;

    const int tid  = threadIdx.x;
    const int lane = tid & 31, warp = tid >> 5;
    const int g = lane >> 2, t = lane & 3;
    const int wr = (warp & 1) * 64, wc = (warp >> 1) * 32;
    const int m0 = blockIdx.y * 128, n0 = blockIdx.x * 128;

    float acc[4][4][4];
#pragma unroll
    for (int i = 0; i < 4; i++)
#pragma unroll
        for (int j = 0; j < 4; j++)
#pragma unroll
            for (int q = 0; q < 4; q++) acc[i][j][q] = 0.0f;

    auto ldAB = [&](int s, int kt) {
#pragma unroll
        for (int q = 0; q < 2; q++) {
            int idx = q * 256 + tid;
            int row = idx >> 2, c = idx & 3;
            cp_async16(As + s * 5120 + row * 40 + c * 8,
                       AH + (size_t)(m0 + row) * K + kt * 32 + c * 8);
        }
#pragma unroll
        for (int q = 0; q < 2; q++) {
            int idx = q * 256 + tid;
            int row = idx >> 2, c = idx & 3;
            cp_async16(Bs + s * 5120 + row * 40 + c * 8,
                       BmH + (size_t)(n0 + row) * K + kt * 32 + c * 8);
        }
        asm volatile("cp.async.commit_group;\n" ::);
    };

    ldAB(0, 0);
    asm volatile("cp.async.wait_group 0;\n" ::);
    __syncthreads();

    for (int kt = 0; kt < nk; kt++) {
        int s = kt & 1;
        bool more = (kt + 1 < nk);
        if (more) ldAB(s ^ 1, kt + 1);

        const __half* Asb = As + s * 5120;
        const __half* Bsb = Bs + s * 5120;
#pragma unroll
        for (int kk = 0; kk < 2; kk++) {
            uint32_t af[4][4];
#pragma unroll
            for (int mt = 0; mt < 4; mt++) {
                int row = wr + mt * 16 + g;
                int col = kk * 16 + 2 * t;
                af[mt][0] = *reinterpret_cast<const uint32_t*>(Asb + row * 40 + col);
                af[mt][1] = *reinterpret_cast<const uint32_t*>(Asb + (row + 8) * 40 + col);
                af[mt][2] = *reinterpret_cast<const uint32_t*>(Asb + row * 40 + col + 8);
                af[mt][3] = *reinterpret_cast<const uint32_t*>(Asb + (row + 8) * 40 + col + 8);
            }
            uint32_t bf[4][2];
#pragma unroll
            for (int nt = 0; nt < 4; nt++) {
                int nl = wc + nt * 8 + g;
                int col = kk * 16 + 2 * t;
                bf[nt][0] = *reinterpret_cast<const uint32_t*>(Bsb + nl * 40 + col);
                bf[nt][1] = *reinterpret_cast<const uint32_t*>(Bsb + nl * 40 + col + 8);
            }
#pragma unroll
            for (int mt = 0; mt < 4; mt++)
#pragma unroll
                for (int nt = 0; nt < 4; nt++)
                    mma_f16(acc[mt][nt], af[mt], bf[nt]);
        }
        if (more) asm volatile("cp.async.wait_group 0;\n" ::);
        __syncthreads();
    }

    // epilogue: + D*u, write out
#pragma unroll
    for (int mt = 0; mt < 4; mt++) {
#pragma unroll
        for (int nt = 0; nt < 4; nt++) {
            int r0 = m0 + wr + mt * 16 + g;
            int cc = n0 + wc + nt * 8 + 2 * t;
            float d0 = Dv[cc], d1 = Dv[cc + 1];
            float v0 = fmaf(d0, U[(size_t)r0 * 256 + cc],     acc[mt][nt][0]);
            float v1 = fmaf(d1, U[(size_t)r0 * 256 + cc + 1], acc[mt][nt][1]);
            float v2 = fmaf(d0, U[(size_t)(r0 + 8) * 256 + cc],     acc[mt][nt][2]);
            float v3 = fmaf(d1, U[(size_t)(r0 + 8) * 256 + cc + 1], acc[mt][nt][3]);
            *reinterpret_cast<float2*>(Out + (size_t)r0 * N + cc) = make_float2(v0, v1);
            *reinterpret_cast<float2*>(Out + (size_t)(r0 + 8) * N + cc) = make_float2(v2, v3);
        }
    }
}

// ---------------------------------------------------------------------------
extern "C" void kernel_launch(void* const* d_in, const int* in_sizes, int n_in,
                              void* d_out, int out_size) {
    const float* u  = (const float*)d_in[0];
    const float* Ad = (const float*)d_in[1];
    const float* Gd = (const float*)d_in[2];
    const float* dt = (const float*)d_in[3];
    const float* Bm = (const float*)d_in[4];
    const float* Cm = (const float*)d_in[5];
    const float* Dv = (const float*)d_in[6];
    float* out = (float*)d_out;

    __half *fptr, *ysptr, *bop, *cop;
    cudaGetSymbolAddress((void**)&fptr,  g_fh);
    cudaGetSymbolAddress((void**)&ysptr, g_ysh);
    cudaGetSymbolAddress((void**)&bop,   g_BopH);
    cudaGetSymbolAddress((void**)&cop,   g_CopH);

    const int smem1 = 128 * 132 * 4;        // 67584 (fp32 scan overlay dominates)
    const int smem2 = 4 * 5120 * 2;         // 40960
    cudaFuncSetAttribute(gemm1_f16,
                         cudaFuncAttributeMaxDynamicSharedMemorySize, smem1);
    cudaFuncSetAttribute(gemm2_f16,
                         cudaFuncAttributeMaxDynamicSharedMemorySize, smem2);

    prep_kernel<<<256, 512>>>(Ad, Gd, dt, Bm, Cm);

    // GEMM1 + fused local scan: f = u @ Bop^T (fp16 out), chunk states -> g_cf
    gemm1_f16<<<dim3(4, 256), 256, smem1>>>(u, bop, fptr);

    scan_combine<<<256, 256>>>();

    // final scan: ys = scan(f), fp16 in/out
    scan_final<<<Bc * NCHUNK, 256>>>();

    // GEMM2: out = ys @ Cop^T + D*u
    gemm2_f16<<<dim3(2, 256), 256, smem2>>>(ysptr, cop, out, u, Dv);
}